// round 12
// baseline (speedup 1.0000x reference)
#include <cuda_runtime.h>
#include <cstdint>
#include <cstddef>

#define Bsz 8
#define Cc  32
#define Oo  64
#define Hh  64
#define Ww  64
#define Kk  9

constexpr int OTILE = 8;                  // o's per block
constexpr int SEG   = Ww * Kk;            // 576 floats per (o,c,h)
constexpr int WTILE = OTILE * SEG;        // 4608 floats per c (18432 B)
constexpr int XROWS = 3;
constexpr int XCOLP = 72;                 // [3]=col -1, [4..67]=cols 0..63, [68]=col 64
constexpr int XTILE = Bsz * XROWS * XCOLP;// 1728 floats per c (6912 B)
constexpr int NBUF  = 3;                  // triple buffer: 2 stages in flight during compute
constexpr int SMEM_BYTES = 32 + NBUF * (WTILE + XTILE) * 4;   // 76064 B -> 3 CTAs/SM
constexpr int WC_STRIDE = Hh * SEG;
constexpr int XC_STRIDE = Hh * Ww;
constexpr uint32_t WSEG_BYTES = SEG * 4;  // 2304
constexpr uint32_t XROW_BYTES = Ww * 4;   // 256

typedef unsigned long long ull;

__device__ __forceinline__ ull pack2(float lo, float hi) {
    ull r; asm("mov.b64 %0, {%1, %2};" : "=l"(r) : "f"(lo), "f"(hi)); return r;
}
__device__ __forceinline__ void unpack2(float& lo, float& hi, ull v) {
    asm("mov.b64 {%0, %1}, %2;" : "=f"(lo), "=f"(hi) : "l"(v));
}
__device__ __forceinline__ void fma2(ull& d, ull a, ull b) {
    asm("fma.rn.f32x2 %0, %1, %2, %0;" : "+l"(d) : "l"(a), "l"(b));
}

__device__ __forceinline__ void mbar_init(uint32_t mbar, uint32_t cnt) {
    asm volatile("mbarrier.init.shared.b64 [%0], %1;" :: "r"(mbar), "r"(cnt) : "memory");
}
__device__ __forceinline__ void mbar_expect_tx(uint32_t mbar, uint32_t bytes) {
    asm volatile("mbarrier.arrive.expect_tx.shared.b64 _, [%0], %1;"
                 :: "r"(mbar), "r"(bytes) : "memory");
}
__device__ __forceinline__ void mbar_wait(uint32_t mbar, uint32_t parity) {
    asm volatile(
        "{\n\t.reg .pred P;\n\t"
        "W%=:\n\t"
        "mbarrier.try_wait.parity.acquire.cta.shared::cta.b64 P, [%0], %1, 0x989680;\n\t"
        "@!P bra W%=;\n\t}"
        :: "r"(mbar), "r"(parity) : "memory");
}
__device__ __forceinline__ void bulk_cp(uint32_t dst, const float* src,
                                        uint32_t bytes, uint32_t mbar) {
    asm volatile("cp.async.bulk.shared::cta.global.mbarrier::complete_tx::bytes "
                 "[%0], [%1], %2, [%3];"
                 :: "r"(dst), "l"(src), "r"(bytes), "r"(mbar) : "memory");
}

__global__ void __launch_bounds__(128, 3)
lc2d_kernel(const float* __restrict__ x,
            const float* __restrict__ wt,
            float* __restrict__ out)
{
    extern __shared__ float smem[];
    const uint32_t sbase = (uint32_t)__cvta_generic_to_shared(smem);
    // header: 3 mbarriers (24 B) padded to 32 B
    float* wsm = smem + 8;                       // [NBUF][WTILE]
    float* xsm = smem + 8 + NBUF * WTILE;        // [NBUF][XTILE]
    const uint32_t wsm_u  = sbase + 32;
    const uint32_t xsm_u  = sbase + 32 + NBUF * WTILE * 4;
    const uint32_t mbar_b = sbase;               // mbar[s] = sbase + 8*s

    const int tid = threadIdx.x;           // 128 threads
    const int w   = tid & 63;
    const int oq  = tid >> 6;              // 0..1
    const int h   = blockIdx.x;
    const int ob  = blockIdx.y * OTILE;
    const int o0  = ob + oq * 4;

    // ---- one-time zero init: halo cols + OOB rows (bulk copies never touch these) ----
    #pragma unroll
    for (int i = 0; i < 2; i++) {          // NBUF*48 = 144 halo slots
        int t = tid + i * 128;
        if (t < NBUF * 48) {
            int bufsel = t / 48;
            int q      = t - bufsel * 48;
            int b      = q / 6;
            int rr     = q - b * 6;
            int r      = rr >> 1;
            int side   = rr & 1;
            xsm[bufsel * XTILE + (b * XROWS + r) * XCOLP + (side ? 68 : 3)] = 0.f;
        }
    }
    if (h == 0 || h == Hh - 1) {           // zero the single OOB row per b, all buffers
        int badrow = (h == 0) ? 0 : 2;
        #pragma unroll
        for (int i = 0; i < 12; i++) {
            int idx = tid + i * 128;       // NBUF*512 = 1536 floats
            if (idx < NBUF * 512) {
                int bufsel = idx >> 9;
                int rem    = idx & 511;
                int b      = rem >> 6;
                int col    = rem & 63;
                xsm[bufsel * XTILE + (b * XROWS + badrow) * XCOLP + 4 + col] = 0.f;
            }
        }
    }

    // ---- staging roles ----
    // threads 64..71 (warp 2): weight segment seg = tid-64  (8 x 2304 B bulks)
    // threads  0..23 (warp 0): x row (b = tid/3, r = tid%3)  (256 B bulks, if valid)
    const int  wseg   = tid - 64;
    const bool is_wst = (tid >= 64 && tid < 64 + OTILE);
    int  wsrc0 = 0; uint32_t wdst_off = 0;
    if (is_wst) {
        wsrc0    = (((ob + wseg) * Cc) * Hh + h) * SEG;
        wdst_off = (uint32_t)(wseg * SEG) * 4;
    }
    const bool is_xst = (tid < 24);
    bool xvalid = false; int xsrc0 = 0; uint32_t xdst_off = 0;
    if (is_xst) {
        int xb_ = tid / 3, xr_ = tid - (tid / 3) * 3;
        int grow = h - 1 + xr_;
        xvalid = (grow >= 0 && grow < Hh);
        xsrc0  = ((xb_ * Cc) * Hh + grow) * Ww;
        xdst_off = (uint32_t)((xb_ * XROWS + xr_) * XCOLP + 4) * 4;
    }
    const int nrows = XROWS - (h == 0) - (h == Hh - 1);
    const uint32_t TXBYTES = OTILE * WSEG_BYTES + (uint32_t)(nrows * Bsz) * XROW_BYTES;

    auto issue_bulks = [&](int c, int slot) {   // channel c -> buffer slot
        const uint32_t mb = mbar_b + (uint32_t)slot * 8;
        if (is_wst)
            bulk_cp(wsm_u + (uint32_t)slot * (WTILE * 4) + wdst_off,
                    wt + wsrc0 + c * WC_STRIDE, WSEG_BYTES, mb);
        if (is_xst && xvalid)
            bulk_cp(xsm_u + (uint32_t)slot * (XTILE * 4) + xdst_off,
                    x + xsrc0 + c * XC_STRIDE, XROW_BYTES, mb);
    };

    // prologue: init + arm all 3 barriers strictly before any bulk issues
    if (tid == 0) {
        #pragma unroll
        for (int s = 0; s < NBUF; s++) {
            mbar_init(mbar_b + s * 8, 1);
            mbar_expect_tx(mbar_b + s * 8, TXBYTES);
        }
    }
    __syncthreads();
    issue_bulks(0, 0);
    issue_bulks(1, 1);
    issue_bulks(2, 2);

    ull acc2[4][4];
    #pragma unroll
    for (int oo = 0; oo < 4; oo++)
        #pragma unroll
        for (int bp = 0; bp < 4; bp++)
            acc2[oo][bp] = 0ull;

    int sl = 0, par = 0;                   // rotating slot + wait parity
    for (int c = 0; c < Cc; c++) {
        mbar_wait(mbar_b + sl * 8, par);   // stage(c) complete (acquire)

        const float* wb = wsm + sl * WTILE + oq * 4 * SEG + w * Kk;
        const float* xb = xsm + sl * XTILE + 3 + w;

        #pragma unroll
        for (int r = 0; r < 3; r++) {
            ull wr2[4][3];
            #pragma unroll
            for (int oo = 0; oo < 4; oo++)
                #pragma unroll
                for (int kk = 0; kk < 3; kk++) {
                    float f = wb[oo * SEG + r * 3 + kk];
                    wr2[oo][kk] = pack2(f, f);
                }
            #pragma unroll
            for (int bp = 0; bp < 4; bp++) {
                const float* xlo = xb + (2 * bp)     * (XROWS * XCOLP) + r * XCOLP;
                const float* xhi = xb + (2 * bp + 1) * (XROWS * XCOLP) + r * XCOLP;
                ull xv2[3];
                #pragma unroll
                for (int kk = 0; kk < 3; kk++)
                    xv2[kk] = pack2(xlo[kk], xhi[kk]);
                #pragma unroll
                for (int oo = 0; oo < 4; oo++)
                    #pragma unroll
                    for (int kk = 0; kk < 3; kk++)
                        fma2(acc2[oo][bp], wr2[oo][kk], xv2[kk]);
            }
        }

        if (c + NBUF < Cc) {
            // re-arm this slot's barrier (all threads passed its wait at top of
            // this iteration), then the CTA barrier proves all reads of slot `sl`
            // are done AND orders the expect_tx before every bulk issue.
            if (tid == 0)
                mbar_expect_tx(mbar_b + sl * 8, TXBYTES);
            __syncthreads();
            issue_bulks(c + NBUF, sl);     // refill just-consumed slot
        }

        if (++sl == NBUF) { sl = 0; par ^= 1; }
    }

    // epilogue: coalesced stores
    float* op = out + ((size_t)o0 * Hh + h) * Ww + w;
    #pragma unroll
    for (int bp = 0; bp < 4; bp++)
        #pragma unroll
        for (int oo = 0; oo < 4; oo++) {
            float lo, hi;
            unpack2(lo, hi, acc2[oo][bp]);
            op[(size_t)((2 * bp)     * Oo + oo) * (Hh * Ww)] = lo;
            op[(size_t)((2 * bp + 1) * Oo + oo) * (Hh * Ww)] = hi;
        }
}

extern "C" void kernel_launch(void* const* d_in, const int* in_sizes, int n_in,
                              void* d_out, int out_size)
{
    const float* x  = (const float*)d_in[0];
    const float* wt = (const float*)d_in[1];
    float* out      = (float*)d_out;

    cudaFuncSetAttribute(lc2d_kernel,
                         cudaFuncAttributeMaxDynamicSharedMemorySize, SMEM_BYTES);
    cudaFuncSetAttribute(lc2d_kernel,
                         cudaFuncAttributePreferredSharedMemoryCarveout, 100);

    dim3 grid(Hh, Oo / OTILE);   // 64 x 8 = 512 blocks of 128 threads
    lc2d_kernel<<<grid, 128, SMEM_BYTES>>>(x, wt, out);
}

// round 13
// speedup vs baseline: 1.3510x; 1.3510x over previous
#include <cuda_runtime.h>
#include <cstdint>
#include <cstddef>

#define Bsz 8
#define Cc  32
#define Oo  64
#define Hh  64
#define Ww  64
#define Kk  9

constexpr int OTILE = 16;                 // o's per block
constexpr int SEG   = Ww * Kk;            // 576 floats per (o,c,h)
constexpr int WTILE = OTILE * SEG;        // 9216 floats per c (36864 B)
constexpr int XROWS = 3;
constexpr int XCOLP = 72;                 // [3]=col -1, [4..67]=cols 0..63, [68]=col 64
constexpr int XTILE = Bsz * XROWS * XCOLP;// 1728 floats per c (6912 B)
constexpr int SMEM_BYTES = 16 + (2 * WTILE + 2 * XTILE) * 4;   // 87568 B -> 2 CTAs/SM
constexpr int WC_STRIDE = Hh * SEG;
constexpr int XC_STRIDE = Hh * Ww;
constexpr uint32_t WSEG_BYTES = SEG * 4;  // 2304
constexpr uint32_t XROW_BYTES = Ww * 4;   // 256

typedef unsigned long long ull;

__device__ __forceinline__ ull pack2(float lo, float hi) {
    ull r; asm("mov.b64 %0, {%1, %2};" : "=l"(r) : "f"(lo), "f"(hi)); return r;
}
__device__ __forceinline__ void unpack2(float& lo, float& hi, ull v) {
    asm("mov.b64 {%0, %1}, %2;" : "=f"(lo), "=f"(hi) : "l"(v));
}
__device__ __forceinline__ void fma2(ull& d, ull a, ull b) {
    asm("fma.rn.f32x2 %0, %1, %2, %0;" : "+l"(d) : "l"(a), "l"(b));
}

__device__ __forceinline__ void mbar_init(uint32_t mbar, uint32_t cnt) {
    asm volatile("mbarrier.init.shared.b64 [%0], %1;" :: "r"(mbar), "r"(cnt) : "memory");
}
__device__ __forceinline__ void mbar_expect_tx(uint32_t mbar, uint32_t bytes) {
    asm volatile("mbarrier.arrive.expect_tx.shared.b64 _, [%0], %1;"
                 :: "r"(mbar), "r"(bytes) : "memory");
}
__device__ __forceinline__ void mbar_wait(uint32_t mbar, uint32_t parity) {
    asm volatile(
        "{\n\t.reg .pred P;\n\t"
        "W%=:\n\t"
        "mbarrier.try_wait.parity.acquire.cta.shared::cta.b64 P, [%0], %1, 0x989680;\n\t"
        "@!P bra W%=;\n\t}"
        :: "r"(mbar), "r"(parity) : "memory");
}
__device__ __forceinline__ void bulk_cp(uint32_t dst, const float* src,
                                        uint32_t bytes, uint32_t mbar) {
    asm volatile("cp.async.bulk.shared::cta.global.mbarrier::complete_tx::bytes "
                 "[%0], [%1], %2, [%3];"
                 :: "r"(dst), "l"(src), "r"(bytes), "r"(mbar) : "memory");
}

__global__ void __launch_bounds__(512, 2)
lc2d_kernel(const float* __restrict__ x,
            const float* __restrict__ wt,
            float* __restrict__ out)
{
    extern __shared__ float smem[];
    const uint32_t sbase = (uint32_t)__cvta_generic_to_shared(smem);
    float* wsm = smem + 4;                 // [2][WTILE]
    float* xsm = smem + 4 + 2 * WTILE;     // [2][XTILE]
    const uint32_t wsm_u = sbase + 16;
    const uint32_t xsm_u = sbase + 16 + 2 * WTILE * 4;
    const uint32_t mbar0 = sbase;
    const uint32_t mbar1 = sbase + 8;

    const int tid = threadIdx.x;           // 512 threads
    const int w   = tid & 63;
    const int oq  = (tid >> 6) & 3;        // 0..3 : o-quad
    const int bq  = tid >> 8;              // 0..1 : batch-quad (4 batches each)
    const int h   = blockIdx.x;
    const int ob  = blockIdx.y * OTILE;
    const int o0  = ob + oq * 4;
    const int b0  = bq * 4;

    // ---- one-time zero init: halo cols + OOB rows (bulks never touch these) ----
    if (tid < 96) {                        // cols 3 and 68 of every (buf,b,row)
        int bufsel = tid / 48;
        int q      = tid - bufsel * 48;
        int b      = q / 6;
        int rr     = q - b * 6;
        int r      = rr >> 1;
        int side   = rr & 1;
        xsm[bufsel * XTILE + (b * XROWS + r) * XCOLP + (side ? 68 : 3)] = 0.f;
    }
    if (h == 0 || h == Hh - 1) {           // single OOB row per b, both buffers
        int badrow = (h == 0) ? 0 : 2;
        #pragma unroll
        for (int i = 0; i < 2; i++) {
            int idx = tid + i * 512;       // 1024 floats: 2 bufs x 8 b x 64 cols
            int bufsel = idx >> 9;
            int rem    = idx & 511;
            int b      = rem >> 6;
            int col    = rem & 63;
            xsm[bufsel * XTILE + (b * XROWS + badrow) * XCOLP + 4 + col] = 0.f;
        }
    }

    // ---- staging roles ----
    // threads 64..79 (warp 2): weight segment seg = tid-64  (16 x 2304 B bulks)
    // threads  0..23 (warp 0): x row (b = tid/3, r = tid%3)  (256 B bulks, if valid)
    const int  wseg   = tid - 64;
    const bool is_wst = (tid >= 64 && tid < 64 + OTILE);
    int  wsrc0 = 0; uint32_t wdst_off = 0;
    if (is_wst) {
        wsrc0    = (((ob + wseg) * Cc) * Hh + h) * SEG;
        wdst_off = (uint32_t)(wseg * SEG) * 4;
    }
    const bool is_xst = (tid < 24);
    bool xvalid = false; int xsrc0 = 0; uint32_t xdst_off = 0;
    if (is_xst) {
        int xb_ = tid / 3, xr_ = tid - (tid / 3) * 3;
        int grow = h - 1 + xr_;
        xvalid = (grow >= 0 && grow < Hh);
        xsrc0  = ((xb_ * Cc) * Hh + grow) * Ww;
        xdst_off = (uint32_t)((xb_ * XROWS + xr_) * XCOLP + 4) * 4;
    }
    const int nrows = XROWS - (h == 0) - (h == Hh - 1);
    const uint32_t TXBYTES = OTILE * WSEG_BYTES + (uint32_t)(nrows * Bsz) * XROW_BYTES;

    auto issue_bulks = [&](int c) {        // channel c -> buffer c&1
        const int buf = c & 1;
        const uint32_t mb = (buf ? mbar1 : mbar0);
        if (is_wst)
            bulk_cp(wsm_u + (uint32_t)buf * (WTILE * 4) + wdst_off,
                    wt + wsrc0 + c * WC_STRIDE, WSEG_BYTES, mb);
        if (is_xst && xvalid)
            bulk_cp(xsm_u + (uint32_t)buf * (XTILE * 4) + xdst_off,
                    x + xsrc0 + c * XC_STRIDE, XROW_BYTES, mb);
    };

    // prologue: arm both barriers strictly before any bulk issues
    if (tid == 0) {
        mbar_init(mbar0, 1);
        mbar_init(mbar1, 1);
        mbar_expect_tx(mbar0, TXBYTES);
        mbar_expect_tx(mbar1, TXBYTES);
    }
    __syncthreads();
    issue_bulks(0);
    issue_bulks(1);

    // accumulators: 4 o's x 2 batch-pairs (batches b0+2bp, b0+2bp+1)
    ull acc2[4][2];
    #pragma unroll
    for (int oo = 0; oo < 4; oo++)
        #pragma unroll
        for (int bp = 0; bp < 2; bp++)
            acc2[oo][bp] = 0ull;

    for (int c = 0; c < Cc; c++) {
        const int cur = c & 1;
        mbar_wait(cur ? mbar1 : mbar0, (c >> 1) & 1);   // stage(c) complete (acquire)

        const float* wb = wsm + cur * WTILE + oq * 4 * SEG + w * Kk;
        const float* xb = xsm + cur * XTILE + (size_t)b0 * (XROWS * XCOLP) + 3 + w;

        #pragma unroll
        for (int r = 0; r < 3; r++) {
            ull wr2[4][3];
            #pragma unroll
            for (int oo = 0; oo < 4; oo++)
                #pragma unroll
                for (int kk = 0; kk < 3; kk++) {
                    float f = wb[oo * SEG + r * 3 + kk];
                    wr2[oo][kk] = pack2(f, f);
                }
            #pragma unroll
            for (int bp = 0; bp < 2; bp++) {
                const float* xlo = xb + (2 * bp)     * (XROWS * XCOLP) + r * XCOLP;
                const float* xhi = xb + (2 * bp + 1) * (XROWS * XCOLP) + r * XCOLP;
                ull xv2[3];
                #pragma unroll
                for (int kk = 0; kk < 3; kk++)
                    xv2[kk] = pack2(xlo[kk], xhi[kk]);
                #pragma unroll
                for (int oo = 0; oo < 4; oo++)
                    #pragma unroll
                    for (int kk = 0; kk < 3; kk++)
                        fma2(acc2[oo][bp], wr2[oo][kk], xv2[kk]);
            }
        }

        if (c + 2 < Cc) {
            // re-arm consumed barrier BEFORE the CTA barrier that releases stagers
            if (tid == 0)
                mbar_expect_tx(cur ? mbar1 : mbar0, TXBYTES);
            __syncthreads();               // all threads done READING buffer `cur`
            issue_bulks(c + 2);            // refill just-consumed buffer
        }
    }

    // epilogue: coalesced stores
    float* op = out + ((size_t)o0 * Hh + h) * Ww + w;
    #pragma unroll
    for (int bp = 0; bp < 2; bp++)
        #pragma unroll
        for (int oo = 0; oo < 4; oo++) {
            float lo, hi;
            unpack2(lo, hi, acc2[oo][bp]);
            op[(size_t)((b0 + 2 * bp)     * Oo + oo) * (Hh * Ww)] = lo;
            op[(size_t)((b0 + 2 * bp + 1) * Oo + oo) * (Hh * Ww)] = hi;
        }
}

extern "C" void kernel_launch(void* const* d_in, const int* in_sizes, int n_in,
                              void* d_out, int out_size)
{
    const float* x  = (const float*)d_in[0];
    const float* wt = (const float*)d_in[1];
    float* out      = (float*)d_out;

    cudaFuncSetAttribute(lc2d_kernel,
                         cudaFuncAttributeMaxDynamicSharedMemorySize, SMEM_BYTES);
    cudaFuncSetAttribute(lc2d_kernel,
                         cudaFuncAttributePreferredSharedMemoryCarveout, 100);

    dim3 grid(Hh, Oo / OTILE);   // 64 x 4 = 256 blocks of 512 threads
    lc2d_kernel<<<grid, 512, SMEM_BYTES>>>(x, wt, out);
}

// round 14
// speedup vs baseline: 1.4223x; 1.0528x over previous
#include <cuda_runtime.h>
#include <cstdint>
#include <cstddef>

#define Bsz 8
#define Cc  32
#define Oo  64
#define Hh  64
#define Ww  64
#define Kk  9

constexpr int OTILE = 16;                 // o's per block, 4 o-quads
constexpr int SEG   = Ww * Kk;            // 576 floats per (o,c,h)
constexpr int WTILE = OTILE * SEG;        // 9216 floats per c (36864 B)
constexpr int XROWS = 3;
constexpr int XCOLP = 72;                 // [3]=col -1, [4..67]=cols 0..63, [68]=col 64
constexpr int XTILE = Bsz * XROWS * XCOLP;// 1728 floats per c (6912 B)
// header: full_w[2][4] at +0..63, full_x[2] at +64..79, pad to 96
constexpr int HDR_BYTES = 96;
constexpr int SMEM_BYTES = HDR_BYTES + (2 * WTILE + 2 * XTILE) * 4; // 87648 -> 2 CTAs/SM
constexpr int WC_STRIDE = Hh * SEG;
constexpr int XC_STRIDE = Hh * Ww;
constexpr uint32_t WSEG_BYTES  = SEG * 4;          // 2304
constexpr uint32_t WGRP_BYTES  = 4 * WSEG_BYTES;   // 9216 per o-quad
constexpr uint32_t XROW_BYTES  = Ww * 4;           // 256

typedef unsigned long long ull;

__device__ __forceinline__ ull pack2(float lo, float hi) {
    ull r; asm("mov.b64 %0, {%1, %2};" : "=l"(r) : "f"(lo), "f"(hi)); return r;
}
__device__ __forceinline__ void unpack2(float& lo, float& hi, ull v) {
    asm("mov.b64 {%0, %1}, %2;" : "=f"(lo), "=f"(hi) : "l"(v));
}
__device__ __forceinline__ void fma2(ull& d, ull a, ull b) {
    asm("fma.rn.f32x2 %0, %1, %2, %0;" : "+l"(d) : "l"(a), "l"(b));
}

__device__ __forceinline__ void mbar_init(uint32_t mbar, uint32_t cnt) {
    asm volatile("mbarrier.init.shared.b64 [%0], %1;" :: "r"(mbar), "r"(cnt) : "memory");
}
__device__ __forceinline__ void mbar_expect_tx(uint32_t mbar, uint32_t bytes) {
    asm volatile("mbarrier.arrive.expect_tx.shared.b64 _, [%0], %1;"
                 :: "r"(mbar), "r"(bytes) : "memory");
}
__device__ __forceinline__ void mbar_wait(uint32_t mbar, uint32_t parity) {
    asm volatile(
        "{\n\t.reg .pred P;\n\t"
        "W%=:\n\t"
        "mbarrier.try_wait.parity.acquire.cta.shared::cta.b64 P, [%0], %1, 0x989680;\n\t"
        "@!P bra W%=;\n\t}"
        :: "r"(mbar), "r"(parity) : "memory");
}
__device__ __forceinline__ void bulk_cp(uint32_t dst, const float* src,
                                        uint32_t bytes, uint32_t mbar) {
    asm volatile("cp.async.bulk.shared::cta.global.mbarrier::complete_tx::bytes "
                 "[%0], [%1], %2, [%3];"
                 :: "r"(dst), "l"(src), "r"(bytes), "r"(mbar) : "memory");
}

__global__ void __launch_bounds__(256, 2)
lc2d_kernel(const float* __restrict__ x,
            const float* __restrict__ wt,
            float* __restrict__ out)
{
    extern __shared__ float smem[];
    const uint32_t sbase = (uint32_t)__cvta_generic_to_shared(smem);
    const uint32_t mb_w  = sbase;          // full_w[buf][g] = mb_w + (buf*4+g)*8
    const uint32_t mb_x  = sbase + 64;     // full_x[buf]    = mb_x + buf*8
    float* wsm = smem + HDR_BYTES / 4;                 // [2][WTILE]
    float* xsm = smem + HDR_BYTES / 4 + 2 * WTILE;     // [2][XTILE]
    const uint32_t wsm_u = sbase + HDR_BYTES;
    const uint32_t xsm_u = sbase + HDR_BYTES + 2 * WTILE * 4;

    const int tid = threadIdx.x;           // 256 threads
    const int w   = tid & 63;
    const int oq  = tid >> 6;              // 0..3 : o-quad == barrier group
    const int h   = blockIdx.x;
    const int ob  = blockIdx.y * OTILE;
    const int o0  = ob + oq * 4;

    // ---- one-time zero init: halo cols + OOB rows (bulks never touch these) ----
    if (tid < 96) {                        // cols 3 and 68 of every (buf,b,row)
        int bufsel = tid / 48;
        int q      = tid - bufsel * 48;
        int b      = q / 6;
        int rr     = q - b * 6;
        int r      = rr >> 1;
        int side   = rr & 1;
        xsm[bufsel * XTILE + (b * XROWS + r) * XCOLP + (side ? 68 : 3)] = 0.f;
    }
    if (h == 0 || h == Hh - 1) {           // single OOB row per b, both buffers
        int badrow = (h == 0) ? 0 : 2;
        #pragma unroll
        for (int i = 0; i < 4; i++) {
            int idx = tid + i * 256;       // 1024 floats: 2 bufs x 8 b x 64 cols
            int bufsel = idx >> 9;
            int rem    = idx & 511;
            int b      = rem >> 6;
            int col    = rem & 63;
            xsm[bufsel * XTILE + (b * XROWS + badrow) * XCOLP + 4 + col] = 0.f;
        }
    }

    // ---- staging roles (same threads as R11; barrier now per o-quad) ----
    const int  wseg   = tid - 64;
    const bool is_wst = (tid >= 64 && tid < 64 + OTILE);
    int  wsrc0 = 0; uint32_t wdst_off = 0; int wgrp = 0;
    if (is_wst) {
        wsrc0    = (((ob + wseg) * Cc) * Hh + h) * SEG;
        wdst_off = (uint32_t)(wseg * SEG) * 4;
        wgrp     = wseg >> 2;              // which o-quad this segment belongs to
    }
    const bool is_xst = (tid < 24);
    bool xvalid = false; int xsrc0 = 0; uint32_t xdst_off = 0;
    if (is_xst) {
        int xb_ = tid / 3, xr_ = tid - (tid / 3) * 3;
        int grow = h - 1 + xr_;
        xvalid = (grow >= 0 && grow < Hh);
        xsrc0  = ((xb_ * Cc) * Hh + grow) * Ww;
        xdst_off = (uint32_t)((xb_ * XROWS + xr_) * XCOLP + 4) * 4;
    }
    const int nrows = XROWS - (h == 0) - (h == Hh - 1);
    const uint32_t XTX = (uint32_t)(nrows * Bsz) * XROW_BYTES;

    auto issue_bulks = [&](int c) {        // channel c -> buffer c&1
        const int buf = c & 1;
        if (is_wst)
            bulk_cp(wsm_u + (uint32_t)buf * (WTILE * 4) + wdst_off,
                    wt + wsrc0 + c * WC_STRIDE, WSEG_BYTES,
                    mb_w + (uint32_t)(buf * 4 + wgrp) * 8);
        if (is_xst && xvalid)
            bulk_cp(xsm_u + (uint32_t)buf * (XTILE * 4) + xdst_off,
                    x + xsrc0 + c * XC_STRIDE, XROW_BYTES,
                    mb_x + (uint32_t)buf * 8);
    };

    // prologue: init + arm all barriers strictly before any bulk issues
    if (tid == 0) {
        #pragma unroll
        for (int buf = 0; buf < 2; buf++) {
            #pragma unroll
            for (int g = 0; g < 4; g++) {
                mbar_init(mb_w + (buf * 4 + g) * 8, 1);
                mbar_expect_tx(mb_w + (buf * 4 + g) * 8, WGRP_BYTES);
            }
            mbar_init(mb_x + buf * 8, 1);
            mbar_expect_tx(mb_x + buf * 8, XTX);
        }
    }
    __syncthreads();
    issue_bulks(0);
    issue_bulks(1);

    ull acc2[4][4];
    #pragma unroll
    for (int oo = 0; oo < 4; oo++)
        #pragma unroll
        for (int bp = 0; bp < 4; bp++)
            acc2[oo][bp] = 0ull;

    for (int c = 0; c < Cc; c++) {
        const int cur = c & 1;
        const int par = (c >> 1) & 1;
        // wait ONLY on this o-quad's weights + x (9.2 KB + x, not 43.8 KB)
        mbar_wait(mb_w + (cur * 4 + oq) * 8, par);
        mbar_wait(mb_x + cur * 8, par);

        // distributed early re-arm: this thread just proved phase completion of
        // its group's barrier, so expect_tx for stage c+2 is safe to merge now.
        if (c + 2 < Cc) {
            if (w == 0)
                mbar_expect_tx(mb_w + (cur * 4 + oq) * 8, WGRP_BYTES);
            if (tid == 0)
                mbar_expect_tx(mb_x + cur * 8, XTX);
        }

        const float* wb = wsm + cur * WTILE + oq * 4 * SEG + w * Kk;
        const float* xb = xsm + cur * XTILE + 3 + w;

        #pragma unroll
        for (int r = 0; r < 3; r++) {
            ull wr2[4][3];
            #pragma unroll
            for (int oo = 0; oo < 4; oo++)
                #pragma unroll
                for (int kk = 0; kk < 3; kk++) {
                    float f = wb[oo * SEG + r * 3 + kk];
                    wr2[oo][kk] = pack2(f, f);
                }
            #pragma unroll
            for (int bp = 0; bp < 4; bp++) {
                const float* xlo = xb + (2 * bp)     * (XROWS * XCOLP) + r * XCOLP;
                const float* xhi = xb + (2 * bp + 1) * (XROWS * XCOLP) + r * XCOLP;
                ull xv2[3];
                #pragma unroll
                for (int kk = 0; kk < 3; kk++)
                    xv2[kk] = pack2(xlo[kk], xhi[kk]);
                #pragma unroll
                for (int oo = 0; oo < 4; oo++)
                    #pragma unroll
                    for (int kk = 0; kk < 3; kk++)
                        fma2(acc2[oo][bp], wr2[oo][kk], xv2[kk]);
            }
        }

        if (c + 2 < Cc) {
            __syncthreads();               // all threads done READING buffer `cur`
            issue_bulks(c + 2);            // refill just-consumed buffer
        }
    }

    // epilogue: coalesced stores
    float* op = out + ((size_t)o0 * Hh + h) * Ww + w;
    #pragma unroll
    for (int bp = 0; bp < 4; bp++)
        #pragma unroll
        for (int oo = 0; oo < 4; oo++) {
            float lo, hi;
            unpack2(lo, hi, acc2[oo][bp]);
            op[(size_t)((2 * bp)     * Oo + oo) * (Hh * Ww)] = lo;
            op[(size_t)((2 * bp + 1) * Oo + oo) * (Hh * Ww)] = hi;
        }
}

extern "C" void kernel_launch(void* const* d_in, const int* in_sizes, int n_in,
                              void* d_out, int out_size)
{
    const float* x  = (const float*)d_in[0];
    const float* wt = (const float*)d_in[1];
    float* out      = (float*)d_out;

    cudaFuncSetAttribute(lc2d_kernel,
                         cudaFuncAttributeMaxDynamicSharedMemorySize, SMEM_BYTES);
    cudaFuncSetAttribute(lc2d_kernel,
                         cudaFuncAttributePreferredSharedMemoryCarveout, 100);

    dim3 grid(Hh, Oo / OTILE);   // 64 x 4 = 256 blocks of 256 threads
    lc2d_kernel<<<grid, 256, SMEM_BYTES>>>(x, wt, out);
}